// round 15
// baseline (speedup 1.0000x reference)
#include <cuda_runtime.h>
#include <cuda_fp16.h>

#define Bv 8
#define Nv 128
#define Tv 256
#define Lv 32
#define Hv 128
#define TTv 224   // T - L

typedef unsigned int u32;

// Scratch (static device globals; allocation-free)
__device__ float g_wsum16[16 * Nv * Hv];   // partial sum_j W_fc[n,j,h] (16 slabs)
__device__ float g_bsum[Nv];               // sum_j b_fc[n,j]
__device__ float g_hsum[Bv * Nv * Hv];     // sum_t h[b,n,t,h]/x[b,n,t+L]
__device__ float g_R[Bv * Nv];             // sum_t 1/x[b,n,t+L]
__device__ u32 g_wh[Nv * 384 * 20];        // W_ih fp16, padded rows (20 u32 = 40 halves)

__device__ __forceinline__ float tanh_fast(float v) {
    float r;
    asm("tanh.approx.f32 %0, %1;" : "=f"(r) : "f"(v));
    return r;
}
__device__ __forceinline__ float sig_fast(float v) {
    return fmaf(0.5f, tanh_fast(0.5f * v), 0.5f);
}
__device__ __forceinline__ void mma16816(float* c, u32 a0, u32 a1, u32 a2, u32 a3,
                                         u32 b0, u32 b1) {
    asm("mma.sync.aligned.m16n8k16.row.col.f32.f16.f16.f32 "
        "{%0,%1,%2,%3}, {%4,%5,%6,%7}, {%8,%9}, {%0,%1,%2,%3};"
        : "+f"(c[0]), "+f"(c[1]), "+f"(c[2]), "+f"(c[3])
        : "r"(a0), "r"(a1), "r"(a2), "r"(a3), "r"(b0), "r"(b1));
}

// ---------------------------------------------------------------------------
// K-1: convert W_ih (gates i,g,o) to fp16, padded 40-elem rows.
// grid (Nv, 3): block = (n, gate); 128 threads = one h column each.
// ---------------------------------------------------------------------------
__global__ void __launch_bounds__(128) k_wprep(const float* __restrict__ Wih) {
    const int n = blockIdx.x, g3 = blockIdx.y;
    const int hh = threadIdx.x;
    const int col = g3 * 128 + hh;
    const int grow = (g3 == 0) ? 0 : (g3 + 1);
    const float* src = Wih + (((size_t)n * 4 + grow) * Hv + hh) * Lv;
    u32* dh = g_wh + ((size_t)n * 384 + col) * 20;
#pragma unroll
    for (int q = 0; q < 16; q++) {
        __half h0 = __float2half_rn(src[2 * q]);
        __half h1 = __float2half_rn(src[2 * q + 1]);
        dh[q] = (u32)__half_as_ushort(h0) | ((u32)__half_as_ushort(h1) << 16);
    }
#pragma unroll
    for (int q = 16; q < 20; q++) dh[q] = 0;
}

// ---------------------------------------------------------------------------
// K0: partial Wsum[n,h] over 16 j-slabs (8 j each); bsum[n] on slab 0.
// ---------------------------------------------------------------------------
__global__ void __launch_bounds__(128) k_prep(const float* __restrict__ Wfc,
                                              const float* __restrict__ bfc) {
    const int n = blockIdx.x, jc = blockIdx.y, h = threadIdx.x;
    const float* p = Wfc + (size_t)n * Nv * Hv + (size_t)jc * 8 * Hv + h;
    float s = 0.f;
#pragma unroll
    for (int j = 0; j < 8; j++) s += p[(size_t)j * Hv];
    g_wsum16[(jc * Nv + n) * Hv + h] = s;

    if (jc == 0) {
        float bvv = bfc[n * Nv + h];
#pragma unroll
        for (int off = 16; off; off >>= 1) bvv += __shfl_xor_sync(0xffffffffu, bvv, off);
        __shared__ float red[4];
        if ((h & 31) == 0) red[h >> 5] = bvv;
        __syncthreads();
        if (h == 0) g_bsum[n] = red[0] + red[1] + red[2] + red[3];
    }
}

// ---------------------------------------------------------------------------
// K1: tensor-core gates — 2-pass (Ah*Bh + Al*Bh), fp16 operands, fp32 accum.
// Structure identical to R14 (smem ~40 KB, barrier-free main loop).
// ---------------------------------------------------------------------------
#define SM_WH    0
#define SM_XS    30720
#define SM_XHA   31744
#define SM_XHB   32256
#define SM_XLA   32768
#define SM_XLB   33280
#define SM_RXS   33792
#define SM_BSM   34688
#define SM_WSM   36224
#define SM_REDX  36736
#define SM_REDR  40320
#define SM_TOT   40352

__global__ void __launch_bounds__(128) k_lstm(const float* __restrict__ x,
                                              const float* __restrict__ bih,
                                              const float* __restrict__ bhh,
                                              float* __restrict__ outX) {
    extern __shared__ __align__(16) unsigned char smraw[];
    float* xs   = (float*)(smraw + SM_XS);
    __half* xha = (__half*)(smraw + SM_XHA);
    __half* xhb = (__half*)(smraw + SM_XHB);
    __half* xla = (__half*)(smraw + SM_XLA);
    __half* xlb = (__half*)(smraw + SM_XLB);
    float* rxs  = (float*)(smraw + SM_RXS);
    float* bsm  = (float*)(smraw + SM_BSM);
    float* wsm  = (float*)(smraw + SM_WSM);
    float* redX = (float*)(smraw + SM_REDX);
    float* redR = (float*)(smraw + SM_REDR);

    const int n = blockIdx.x, b = blockIdx.y;
    const int tid = threadIdx.x;
    const int lane = tid & 31, w = tid >> 5;
    const int gid = lane >> 2, tig = lane & 3;

    // ---- stage x ----
    const float* xrow = x + ((size_t)b * Nv + n) * Tv;
    xs[tid] = xrow[tid];
    xs[tid + 128] = xrow[tid + 128];
    __syncthreads();

    // ---- fp16 split tables (xhb[i] = xh[i+1] for odd-aligned pairs) ----
#pragma unroll
    for (int rep = 0; rep < 2; rep++) {
        const int i = tid + rep * 128;
        const float f = xs[i];
        const __half hh = __float2half_rn(f);
        const __half ll = __float2half_rn(f - __half2float(hh));
        xha[i] = hh; xla[i] = ll;
        if (i > 0) { xhb[i - 1] = hh; xlb[i - 1] = ll; }
    }
    for (int i = tid; i < TTv; i += 128) rxs[i] = 1.0f / xs[i + Lv];

    // ---- stage W fp16 (flat copy, padded rows match gmem layout) ----
    {
        const int4* sh = (const int4*)(g_wh + (size_t)n * 7680);
        int4* dh = (int4*)(smraw + SM_WH);
#pragma unroll
        for (int q = 0; q < 15; q++)
            dh[tid + q * 128] = sh[tid + q * 128];
    }

    // ---- biases and wsum into smem ----
#pragma unroll
    for (int rep = 0; rep < 3; rep++) {
        const int col = tid + rep * 128;
        const int g3 = col >> 7, hh = col & 127;
        const int grow = (g3 == 0) ? 0 : (g3 + 1);
        const size_t idx = (size_t)n * 4 * Hv + grow * Hv + hh;
        bsm[col] = bih[idx] + bhh[idx];
    }
    {
        const int nh = n * Hv + tid;
        float ws = 0.f;
#pragma unroll
        for (int s16 = 0; s16 < 16; s16++) ws += g_wsum16[s16 * Nv * Hv + nh];
        wsm[tid] = ws;
    }
    __syncthreads();

    // ---- R[b,n] ----
    {
        float r = 0.f;
        for (int i = tid; i < TTv; i += 128) r += rxs[i];
#pragma unroll
        for (int off = 16; off; off >>= 1) r += __shfl_xor_sync(0xffffffffu, r, off);
        if (lane == 0) redR[w] = r;
        __syncthreads();
        if (tid == 0) g_R[b * Nv + n] = redR[0] + redR[1] + redR[2] + redR[3];
    }

    // ---- per-thread constants ----
    float wsum8[8];
#pragma unroll
    for (int j = 0; j < 4; j++)
#pragma unroll
        for (int cc = 0; cc < 2; cc++)
            wsum8[j * 2 + cc] = wsm[(w << 5) + j * 8 + (tig << 1) + cc];

    const int odd = gid & 1;
    const int pb = gid + 2 * tig - odd;          // even
    const u32* xaH = (const u32*)(odd ? (void*)xhb : (void*)xha);
    const u32* xaL = (const u32*)(odd ? (void*)xlb : (void*)xla);
    const u32* WhU = (const u32*)(smraw + SM_WH);

    float hs[8];
#pragma unroll
    for (int e = 0; e < 8; e++) hs[e] = 0.f;

    // ================= main loop: 14 slabs of 16 t, NO barriers =============
    for (int slab = 0; slab < 14; slab++) {
        const int t0 = slab * 16;
        const int q = (t0 + pb) >> 1;

        u32 Ah[5], Al[5];
#pragma unroll
        for (int i = 0; i < 5; i++) { Ah[i] = xaH[q + 4 * i]; Al[i] = xaL[q + 4 * i]; }

        float c[48];
        // C init = biases (per tile: cols 2tig, 2tig+1; both rows share)
#pragma unroll
        for (int g3 = 0; g3 < 3; g3++)
#pragma unroll
            for (int j = 0; j < 4; j++) {
                const int col0 = g3 * 128 + (w << 5) + (j << 3) + (tig << 1);
                const float b0 = bsm[col0], b1 = bsm[col0 + 1];
                float* ct = c + (g3 * 4 + j) * 4;
                ct[0] = b0; ct[1] = b1; ct[2] = b0; ct[3] = b1;
            }

        // MMA: 12 tiles x 2 k-steps x 2 passes (Ah*Bh + Al*Bh)
#pragma unroll
        for (int g3 = 0; g3 < 3; g3++)
#pragma unroll
            for (int j = 0; j < 4; j++) {
                const int colb = g3 * 128 + (w << 5) + (j << 3) + gid;
                const u32* br_h = WhU + colb * 20;
                float* ct = c + (g3 * 4 + j) * 4;
#pragma unroll
                for (int ks = 0; ks < 2; ks++) {
                    const u32 bh0 = br_h[8 * ks + tig], bh1 = br_h[8 * ks + tig + 4];
                    const u32 a0 = Ah[2 * ks], a12 = Ah[2 * ks + 1], a3 = Ah[2 * ks + 2];
                    const u32 e0 = Al[2 * ks], e12 = Al[2 * ks + 1], e3 = Al[2 * ks + 2];
                    mma16816(ct, a0, a12, a12, a3, bh0, bh1);
                    mma16816(ct, e0, e12, e12, e3, bh0, bh1);
                }
            }

        // Epilogue: register-local activations
        const float rx0 = rxs[t0 + gid];
        const float rx1 = rxs[t0 + gid + 8];
        float sxr0 = 0.f, sxr1 = 0.f;
#pragma unroll
        for (int j = 0; j < 4; j++)
#pragma unroll
            for (int cc = 0; cc < 2; cc++) {
                const float ws = wsum8[j * 2 + cc];
#pragma unroll
                for (int rr = 0; rr < 2; rr++) {
                    const int idx = rr * 2 + cc;
                    const float pi = c[(0 * 4 + j) * 4 + idx];
                    const float pg = c[(1 * 4 + j) * 4 + idx];
                    const float po = c[(2 * 4 + j) * 4 + idx];
                    const float cv = sig_fast(pi) * tanh_fast(pg);
                    const float hv = sig_fast(po) * tanh_fast(cv);
                    hs[j * 2 + cc] = fmaf(hv, rr ? rx1 : rx0, hs[j * 2 + cc]);
                    if (rr) sxr1 = fmaf(hv, ws, sxr1);
                    else    sxr0 = fmaf(hv, ws, sxr0);
                }
            }
        // reduce over tig (h within warp): xor 1, 2
        sxr0 += __shfl_xor_sync(0xffffffffu, sxr0, 1);
        sxr0 += __shfl_xor_sync(0xffffffffu, sxr0, 2);
        sxr1 += __shfl_xor_sync(0xffffffffu, sxr1, 1);
        sxr1 += __shfl_xor_sync(0xffffffffu, sxr1, 2);
        if (tig == 0) {
            redX[w * TTv + t0 + gid] = sxr0;
            redX[w * TTv + t0 + gid + 8] = sxr1;
        }
    }

    // ---- Hsum: reduce over gid (xor 4,8,16), lanes gid==0 store ----
#pragma unroll
    for (int e = 0; e < 8; e++) {
        float v = hs[e];
        v += __shfl_xor_sync(0xffffffffu, v, 4);
        v += __shfl_xor_sync(0xffffffffu, v, 8);
        v += __shfl_xor_sync(0xffffffffu, v, 16);
        hs[e] = v;
    }
    if (gid == 0) {
#pragma unroll
        for (int j = 0; j < 4; j++)
#pragma unroll
            for (int cc = 0; cc < 2; cc++) {
                const int h = (w << 5) + j * 8 + (tig << 1) + cc;
                g_hsum[((size_t)b * Nv + n) * Hv + h] = hs[j * 2 + cc];
            }
    }

    // ---- X_hat: sum 4 warp partials per t ----
    const float bsum_n = g_bsum[n];
    __syncthreads();
    for (int i = tid; i < TTv; i += 128) {
        const float s = redX[i] + redX[TTv + i] + redX[2 * TTv + i] + redX[3 * TTv + i];
        outX[((size_t)b * TTv + i) * Nv + n] = s + bsum_n + 1e-6f;
    }
}

// ---------------------------------------------------------------------------
// K2: G[b,j,n]. grid (Nv, 8); warp owns 4 j's; butterfly reduction with
// accumulator halving (9 SHFL per j). Lane's final acc holds
// b = 4*bit16 + 2*bit8 + bit4; lanes with (lane&3)==0 store.
// ---------------------------------------------------------------------------
__global__ void __launch_bounds__(128) k_gout(const float* __restrict__ Wfc,
                                              const float* __restrict__ bfc,
                                              float* __restrict__ outG) {
    const int n = blockIdx.x, jc = blockIdx.y;
    const int tid = threadIdx.x;
    const int w = tid >> 5, lane = tid & 31;
    const int j0 = jc * 16 + w * 4;

    const int bl_ = ((lane >> 4) & 1) * 4 + ((lane >> 3) & 1) * 2 + ((lane >> 2) & 1);
    const float Rb = g_R[bl_ * Nv + n];

    float Hl[Bv][4];
#pragma unroll
    for (int bb = 0; bb < Bv; bb++) {
        const float4 v = ((const float4*)(g_hsum + ((size_t)bb * Nv + n) * Hv))[lane];
        Hl[bb][0] = v.x; Hl[bb][1] = v.y; Hl[bb][2] = v.z; Hl[bb][3] = v.w;
    }

    const float sc = 1.0f / (float)TTv;
#pragma unroll
    for (int jj = 0; jj < 4; jj++) {
        const int j = j0 + jj;
        const float4 wv = ((const float4*)(Wfc + ((size_t)n * Nv + j) * Hv))[lane];
        float acc[Bv];
#pragma unroll
        for (int bb = 0; bb < Bv; bb++) {
            acc[bb] = wv.x * Hl[bb][0] + wv.y * Hl[bb][1] +
                      wv.z * Hl[bb][2] + wv.w * Hl[bb][3];
        }
        // butterfly with accumulator halving: steps 16, 8, 4
#pragma unroll
        for (int i = 0; i < 4; i++) {
            const float sent = (lane & 16) ? acc[i] : acc[i + 4];
            const float kept = (lane & 16) ? acc[i + 4] : acc[i];
            acc[i] = kept + __shfl_xor_sync(0xffffffffu, sent, 16);
        }
#pragma unroll
        for (int i = 0; i < 2; i++) {
            const float sent = (lane & 8) ? acc[i] : acc[i + 2];
            const float kept = (lane & 8) ? acc[i + 2] : acc[i];
            acc[i] = kept + __shfl_xor_sync(0xffffffffu, sent, 8);
        }
        {
            const float sent = (lane & 4) ? acc[0] : acc[1];
            const float kept = (lane & 4) ? acc[1] : acc[0];
            acc[0] = kept + __shfl_xor_sync(0xffffffffu, sent, 4);
        }
        acc[0] += __shfl_xor_sync(0xffffffffu, acc[0], 2);
        acc[0] += __shfl_xor_sync(0xffffffffu, acc[0], 1);

        if ((lane & 3) == 0) {
            const float bj = bfc[n * Nv + j];
            outG[((size_t)bl_ * Nv + j) * Nv + n] = (acc[0] + bj * Rb) * sc;
        }
    }
}

// ---------------------------------------------------------------------------
extern "C" void kernel_launch(void* const* d_in, const int* in_sizes, int n_in,
                              void* d_out, int out_size) {
    (void)in_sizes; (void)n_in; (void)out_size;
    const float* x   = (const float*)d_in[0];
    const float* Wih = (const float*)d_in[1];
    const float* bih = (const float*)d_in[2];
    const float* bhh = (const float*)d_in[3];
    const float* Wfc = (const float*)d_in[4];
    const float* bfc = (const float*)d_in[5];

    float* outG = (float*)d_out;                       // (B, N, N)
    float* outX = outG + (size_t)Bv * Nv * Nv;         // (B, Ttau, N)

    cudaFuncSetAttribute(k_lstm, cudaFuncAttributeMaxDynamicSharedMemorySize, SM_TOT);

    dim3 gw(Nv, 3);
    k_wprep<<<gw, 128>>>(Wih);
    dim3 g0(Nv, 16);
    k_prep<<<g0, 128>>>(Wfc, bfc);
    dim3 g1(Nv, Bv);
    k_lstm<<<g1, 128, SM_TOT>>>(x, bih, bhh, outX);
    dim3 g2(Nv, 8);
    k_gout<<<g2, 128>>>(Wfc, bfc, outG);
}

// round 16
// speedup vs baseline: 1.1892x; 1.1892x over previous
#include <cuda_runtime.h>
#include <cuda_fp16.h>

#define Bv 8
#define Nv 128
#define Tv 256
#define Lv 32
#define Hv 128
#define TTv 224   // T - L

typedef unsigned int u32;

// Scratch (static device globals; allocation-free)
__device__ float g_wsum4[4 * Nv * Hv];     // partial sum_j W_fc[n,j,h]
__device__ float g_bsum[Nv];               // sum_j b_fc[n,j]
__device__ float g_hsum[Bv * Nv * Hv];     // sum_t h[b,n,t,h]/x[b,n,t+L]
__device__ float g_R[Bv * Nv];             // sum_t 1/x[b,n,t+L]
__device__ u32 g_wh[Nv * 384 * 20];        // W_ih fp16, padded rows (20 u32 = 40 halves)

__device__ __forceinline__ float tanh_fast(float v) {
    float r;
    asm("tanh.approx.f32 %0, %1;" : "=f"(r) : "f"(v));
    return r;
}
__device__ __forceinline__ float sig_fast(float v) {
    return fmaf(0.5f, tanh_fast(0.5f * v), 0.5f);
}
__device__ __forceinline__ void mma16816(float* c, u32 a0, u32 a1, u32 a2, u32 a3,
                                         u32 b0, u32 b1) {
    asm("mma.sync.aligned.m16n8k16.row.col.f32.f16.f16.f32 "
        "{%0,%1,%2,%3}, {%4,%5,%6,%7}, {%8,%9}, {%0,%1,%2,%3};"
        : "+f"(c[0]), "+f"(c[1]), "+f"(c[2]), "+f"(c[3])
        : "r"(a0), "r"(a1), "r"(a2), "r"(a3), "r"(b0), "r"(b1));
}

// ---------------------------------------------------------------------------
// K-1: convert W_ih (gates i,g,o) to fp16, padded 40-elem rows.
// Block n, 384 threads (one per gate-h column).  (R14 grid, fp16 payload.)
// ---------------------------------------------------------------------------
__global__ void __launch_bounds__(384) k_wprep(const float* __restrict__ Wih) {
    const int n = blockIdx.x, col = threadIdx.x;
    const int g3 = col >> 7, hh = col & 127;
    const int grow = (g3 == 0) ? 0 : (g3 + 1);
    const float* src = Wih + (((size_t)n * 4 + grow) * Hv + hh) * Lv;
    u32* dh = g_wh + ((size_t)n * 384 + col) * 20;
#pragma unroll
    for (int q = 0; q < 16; q++) {
        __half h0 = __float2half_rn(src[2 * q]);
        __half h1 = __float2half_rn(src[2 * q + 1]);
        dh[q] = (u32)__half_as_ushort(h0) | ((u32)__half_as_ushort(h1) << 16);
    }
#pragma unroll
    for (int q = 16; q < 20; q++) dh[q] = 0;
}

// ---------------------------------------------------------------------------
// K0: partial Wsum[n,h] over 4 j-slabs (32 j each); bsum[n].  (R14 version.)
// ---------------------------------------------------------------------------
__global__ void __launch_bounds__(128) k_prep(const float* __restrict__ Wfc,
                                              const float* __restrict__ bfc) {
    const int n = blockIdx.x, jc = blockIdx.y, h = threadIdx.x;
    const float* p = Wfc + (size_t)n * Nv * Hv + (size_t)jc * 32 * Hv + h;
    float s = 0.f;
#pragma unroll
    for (int j = 0; j < 32; j++) s += p[(size_t)j * Hv];
    g_wsum4[(jc * Nv + n) * Hv + h] = s;

    if (jc == 0) {
        float bvv = bfc[n * Nv + h];
#pragma unroll
        for (int off = 16; off; off >>= 1) bvv += __shfl_xor_sync(0xffffffffu, bvv, off);
        __shared__ float red[4];
        if ((h & 31) == 0) red[h >> 5] = bvv;
        __syncthreads();
        if (h == 0) g_bsum[n] = red[0] + red[1] + red[2] + red[3];
    }
}

// ---------------------------------------------------------------------------
// K1: tensor-core gates — 2-pass (Ah*Bh + Al*Bh), fp16 operands, fp32 accum.
// R14 structure (4-slab wsum), fp16 payload.
// ---------------------------------------------------------------------------
#define SM_WH    0
#define SM_XS    30720
#define SM_XHA   31744
#define SM_XHB   32256
#define SM_XLA   32768
#define SM_XLB   33280
#define SM_RXS   33792
#define SM_BSM   34688
#define SM_WSM   36224
#define SM_REDX  36736
#define SM_REDR  40320
#define SM_TOT   40352

__global__ void __launch_bounds__(128) k_lstm(const float* __restrict__ x,
                                              const float* __restrict__ bih,
                                              const float* __restrict__ bhh,
                                              float* __restrict__ outX) {
    extern __shared__ __align__(16) unsigned char smraw[];
    float* xs   = (float*)(smraw + SM_XS);
    __half* xha = (__half*)(smraw + SM_XHA);
    __half* xhb = (__half*)(smraw + SM_XHB);
    __half* xla = (__half*)(smraw + SM_XLA);
    __half* xlb = (__half*)(smraw + SM_XLB);
    float* rxs  = (float*)(smraw + SM_RXS);
    float* bsm  = (float*)(smraw + SM_BSM);
    float* wsm  = (float*)(smraw + SM_WSM);
    float* redX = (float*)(smraw + SM_REDX);
    float* redR = (float*)(smraw + SM_REDR);

    const int n = blockIdx.x, b = blockIdx.y;
    const int tid = threadIdx.x;
    const int lane = tid & 31, w = tid >> 5;
    const int gid = lane >> 2, tig = lane & 3;

    // ---- stage x ----
    const float* xrow = x + ((size_t)b * Nv + n) * Tv;
    xs[tid] = xrow[tid];
    xs[tid + 128] = xrow[tid + 128];
    __syncthreads();

    // ---- fp16 split tables (xhb[i] = xh[i+1] for odd-aligned pairs) ----
#pragma unroll
    for (int rep = 0; rep < 2; rep++) {
        const int i = tid + rep * 128;
        const float f = xs[i];
        const __half hh = __float2half_rn(f);
        const __half ll = __float2half_rn(f - __half2float(hh));
        xha[i] = hh; xla[i] = ll;
        if (i > 0) { xhb[i - 1] = hh; xlb[i - 1] = ll; }
    }
    for (int i = tid; i < TTv; i += 128) rxs[i] = 1.0f / xs[i + Lv];

    // ---- stage W fp16 (flat copy, padded rows match gmem layout) ----
    {
        const int4* sh = (const int4*)(g_wh + (size_t)n * 7680);
        int4* dh = (int4*)(smraw + SM_WH);
#pragma unroll
        for (int q = 0; q < 15; q++)
            dh[tid + q * 128] = sh[tid + q * 128];
    }

    // ---- biases and wsum into smem ----
#pragma unroll
    for (int rep = 0; rep < 3; rep++) {
        const int col = tid + rep * 128;
        const int g3 = col >> 7, hh = col & 127;
        const int grow = (g3 == 0) ? 0 : (g3 + 1);
        const size_t idx = (size_t)n * 4 * Hv + grow * Hv + hh;
        bsm[col] = bih[idx] + bhh[idx];
    }
    {
        const int nh = n * Hv + tid;
        wsm[tid] = g_wsum4[nh] + g_wsum4[Nv * Hv + nh] +
                   g_wsum4[2 * Nv * Hv + nh] + g_wsum4[3 * Nv * Hv + nh];
    }
    __syncthreads();

    // ---- R[b,n] ----
    {
        float r = 0.f;
        for (int i = tid; i < TTv; i += 128) r += rxs[i];
#pragma unroll
        for (int off = 16; off; off >>= 1) r += __shfl_xor_sync(0xffffffffu, r, off);
        if (lane == 0) redR[w] = r;
        __syncthreads();
        if (tid == 0) g_R[b * Nv + n] = redR[0] + redR[1] + redR[2] + redR[3];
    }

    // ---- per-thread constants ----
    float wsum8[8];
#pragma unroll
    for (int j = 0; j < 4; j++)
#pragma unroll
        for (int cc = 0; cc < 2; cc++)
            wsum8[j * 2 + cc] = wsm[(w << 5) + j * 8 + (tig << 1) + cc];

    const int odd = gid & 1;
    const int pb = gid + 2 * tig - odd;          // even
    const u32* xaH = (const u32*)(odd ? (void*)xhb : (void*)xha);
    const u32* xaL = (const u32*)(odd ? (void*)xlb : (void*)xla);
    const u32* WhU = (const u32*)(smraw + SM_WH);

    float hs[8];
#pragma unroll
    for (int e = 0; e < 8; e++) hs[e] = 0.f;

    // ================= main loop: 14 slabs of 16 t, NO barriers =============
    for (int slab = 0; slab < 14; slab++) {
        const int t0 = slab * 16;
        const int q = (t0 + pb) >> 1;

        u32 Ah[5], Al[5];
#pragma unroll
        for (int i = 0; i < 5; i++) { Ah[i] = xaH[q + 4 * i]; Al[i] = xaL[q + 4 * i]; }

        float c[48];
        // C init = biases (per tile: cols 2tig, 2tig+1; both rows share)
#pragma unroll
        for (int g3 = 0; g3 < 3; g3++)
#pragma unroll
            for (int j = 0; j < 4; j++) {
                const int col0 = g3 * 128 + (w << 5) + (j << 3) + (tig << 1);
                const float b0 = bsm[col0], b1 = bsm[col0 + 1];
                float* ct = c + (g3 * 4 + j) * 4;
                ct[0] = b0; ct[1] = b1; ct[2] = b0; ct[3] = b1;
            }

        // MMA: 12 tiles x 2 k-steps x 2 passes (Ah*Bh + Al*Bh)
#pragma unroll
        for (int g3 = 0; g3 < 3; g3++)
#pragma unroll
            for (int j = 0; j < 4; j++) {
                const int colb = g3 * 128 + (w << 5) + (j << 3) + gid;
                const u32* br_h = WhU + colb * 20;
                float* ct = c + (g3 * 4 + j) * 4;
#pragma unroll
                for (int ks = 0; ks < 2; ks++) {
                    const u32 bh0 = br_h[8 * ks + tig], bh1 = br_h[8 * ks + tig + 4];
                    const u32 a0 = Ah[2 * ks], a12 = Ah[2 * ks + 1], a3 = Ah[2 * ks + 2];
                    const u32 e0 = Al[2 * ks], e12 = Al[2 * ks + 1], e3 = Al[2 * ks + 2];
                    mma16816(ct, a0, a12, a12, a3, bh0, bh1);
                    mma16816(ct, e0, e12, e12, e3, bh0, bh1);
                }
            }

        // Epilogue: register-local activations
        const float rx0 = rxs[t0 + gid];
        const float rx1 = rxs[t0 + gid + 8];
        float sxr0 = 0.f, sxr1 = 0.f;
#pragma unroll
        for (int j = 0; j < 4; j++)
#pragma unroll
            for (int cc = 0; cc < 2; cc++) {
                const float ws = wsum8[j * 2 + cc];
#pragma unroll
                for (int rr = 0; rr < 2; rr++) {
                    const int idx = rr * 2 + cc;
                    const float pi = c[(0 * 4 + j) * 4 + idx];
                    const float pg = c[(1 * 4 + j) * 4 + idx];
                    const float po = c[(2 * 4 + j) * 4 + idx];
                    const float cv = sig_fast(pi) * tanh_fast(pg);
                    const float hv = sig_fast(po) * tanh_fast(cv);
                    hs[j * 2 + cc] = fmaf(hv, rr ? rx1 : rx0, hs[j * 2 + cc]);
                    if (rr) sxr1 = fmaf(hv, ws, sxr1);
                    else    sxr0 = fmaf(hv, ws, sxr0);
                }
            }
        // reduce over tig (h within warp): xor 1, 2
        sxr0 += __shfl_xor_sync(0xffffffffu, sxr0, 1);
        sxr0 += __shfl_xor_sync(0xffffffffu, sxr0, 2);
        sxr1 += __shfl_xor_sync(0xffffffffu, sxr1, 1);
        sxr1 += __shfl_xor_sync(0xffffffffu, sxr1, 2);
        if (tig == 0) {
            redX[w * TTv + t0 + gid] = sxr0;
            redX[w * TTv + t0 + gid + 8] = sxr1;
        }
    }

    // ---- Hsum: reduce over gid (xor 4,8,16), lanes gid==0 store ----
#pragma unroll
    for (int e = 0; e < 8; e++) {
        float v = hs[e];
        v += __shfl_xor_sync(0xffffffffu, v, 4);
        v += __shfl_xor_sync(0xffffffffu, v, 8);
        v += __shfl_xor_sync(0xffffffffu, v, 16);
        hs[e] = v;
    }
    if (gid == 0) {
#pragma unroll
        for (int j = 0; j < 4; j++)
#pragma unroll
            for (int cc = 0; cc < 2; cc++) {
                const int h = (w << 5) + j * 8 + (tig << 1) + cc;
                g_hsum[((size_t)b * Nv + n) * Hv + h] = hs[j * 2 + cc];
            }
    }

    // ---- X_hat: sum 4 warp partials per t ----
    const float bsum_n = g_bsum[n];
    __syncthreads();
    for (int i = tid; i < TTv; i += 128) {
        const float s = redX[i] + redX[TTv + i] + redX[2 * TTv + i] + redX[3 * TTv + i];
        outX[((size_t)b * TTv + i) * Nv + n] = s + bsum_n + 1e-6f;
    }
}

// ---------------------------------------------------------------------------
// K2: G[b,j,n]. grid (Nv, 8); warp owns 4 j's; butterfly reduction with
// accumulator halving (9 SHFL per j).
// ---------------------------------------------------------------------------
__global__ void __launch_bounds__(128) k_gout(const float* __restrict__ Wfc,
                                              const float* __restrict__ bfc,
                                              float* __restrict__ outG) {
    const int n = blockIdx.x, jc = blockIdx.y;
    const int tid = threadIdx.x;
    const int w = tid >> 5, lane = tid & 31;
    const int j0 = jc * 16 + w * 4;

    const int bl_ = ((lane >> 4) & 1) * 4 + ((lane >> 3) & 1) * 2 + ((lane >> 2) & 1);
    const float Rb = g_R[bl_ * Nv + n];

    float Hl[Bv][4];
#pragma unroll
    for (int bb = 0; bb < Bv; bb++) {
        const float4 v = ((const float4*)(g_hsum + ((size_t)bb * Nv + n) * Hv))[lane];
        Hl[bb][0] = v.x; Hl[bb][1] = v.y; Hl[bb][2] = v.z; Hl[bb][3] = v.w;
    }

    const float sc = 1.0f / (float)TTv;
#pragma unroll
    for (int jj = 0; jj < 4; jj++) {
        const int j = j0 + jj;
        const float4 wv = ((const float4*)(Wfc + ((size_t)n * Nv + j) * Hv))[lane];
        float acc[Bv];
#pragma unroll
        for (int bb = 0; bb < Bv; bb++) {
            acc[bb] = wv.x * Hl[bb][0] + wv.y * Hl[bb][1] +
                      wv.z * Hl[bb][2] + wv.w * Hl[bb][3];
        }
        // butterfly with accumulator halving: steps 16, 8, 4
#pragma unroll
        for (int i = 0; i < 4; i++) {
            const float sent = (lane & 16) ? acc[i] : acc[i + 4];
            const float kept = (lane & 16) ? acc[i + 4] : acc[i];
            acc[i] = kept + __shfl_xor_sync(0xffffffffu, sent, 16);
        }
#pragma unroll
        for (int i = 0; i < 2; i++) {
            const float sent = (lane & 8) ? acc[i] : acc[i + 2];
            const float kept = (lane & 8) ? acc[i + 2] : acc[i];
            acc[i] = kept + __shfl_xor_sync(0xffffffffu, sent, 8);
        }
        {
            const float sent = (lane & 4) ? acc[0] : acc[1];
            const float kept = (lane & 4) ? acc[1] : acc[0];
            acc[0] = kept + __shfl_xor_sync(0xffffffffu, sent, 4);
        }
        acc[0] += __shfl_xor_sync(0xffffffffu, acc[0], 2);
        acc[0] += __shfl_xor_sync(0xffffffffu, acc[0], 1);

        if ((lane & 3) == 0) {
            const float bj = bfc[n * Nv + j];
            outG[((size_t)bl_ * Nv + j) * Nv + n] = (acc[0] + bj * Rb) * sc;
        }
    }
}

// ---------------------------------------------------------------------------
extern "C" void kernel_launch(void* const* d_in, const int* in_sizes, int n_in,
                              void* d_out, int out_size) {
    (void)in_sizes; (void)n_in; (void)out_size;
    const float* x   = (const float*)d_in[0];
    const float* Wih = (const float*)d_in[1];
    const float* bih = (const float*)d_in[2];
    const float* bhh = (const float*)d_in[3];
    const float* Wfc = (const float*)d_in[4];
    const float* bfc = (const float*)d_in[5];

    float* outG = (float*)d_out;                       // (B, N, N)
    float* outX = outG + (size_t)Bv * Nv * Nv;         // (B, Ttau, N)

    cudaFuncSetAttribute(k_lstm, cudaFuncAttributeMaxDynamicSharedMemorySize, SM_TOT);

    k_wprep<<<Nv, 384>>>(Wih);
    dim3 g0(Nv, 4);
    k_prep<<<g0, 128>>>(Wfc, bfc);
    dim3 g1(Nv, Bv);
    k_lstm<<<g1, 128, SM_TOT>>>(x, bih, bhh, outX);
    dim3 g2(Nv, 8);
    k_gout<<<g2, 128>>>(Wfc, bfc, outG);
}